// round 5
// baseline (speedup 1.0000x reference)
#include <cuda_runtime.h>
#include <math.h>

typedef unsigned long long ull;

#define BB 32
#define LSEQ 512
#define EIN 512
#define NMARKF 4
#define DMODEL 512
#define NHEAD 8
#define DHEAD 64
#define DFFN 2048
#define NTOK 516
#define TPAD 520
#define NHASHR 4
#define NBKT 130
#define BHD (BB*NHEAD)      /* 256 */
#define NCH 520
#define JTOT 2080           /* NHASH * TPAD */
#define MROWS (BB*TPAD)     /* 16640 */

// ---------------- scratch (device globals; no allocation allowed) -------------
__device__ __align__(16) float g_means[BB*EIN];
__device__ __align__(16) float g_stdev[BB*EIN];
__device__ __align__(16) float g_tok[MROWS*LSEQ];
__device__ __align__(16) float g_x[MROWS*DMODEL];
__device__ __align__(16) float g_qk[MROWS*DMODEL];
__device__ __align__(16) float g_vv[MROWS*DMODEL];
__device__ __align__(16) float g_t2[MROWS*DMODEL];
__device__ __align__(16) float g_ff[MROWS*DFFN];
__device__ __align__(16) float g_oh[(size_t)BHD*NHASHR*TPAD*DHEAD];
__device__ __align__(16) float g_lse[BHD*JTOT];
__device__ unsigned g_keys[BHD*JTOT];
__device__ int g_stk[BHD*JTOT];
__device__ float g_dec[BB];

// ---------------- RevIN stats ------------------------------------------------
__global__ void k_revin(const float* __restrict__ x_enc) {
    int idx = blockIdx.x * blockDim.x + threadIdx.x;
    if (idx >= BB*EIN) return;
    int b = idx >> 9, e = idx & 511;
    const float* p = x_enc + (size_t)b*LSEQ*EIN + e;
    float s = 0.f;
    for (int l = 0; l < LSEQ; l++) s += p[(size_t)l*EIN];
    float mean = s * (1.f/LSEQ);
    float q = 0.f;
    for (int l = 0; l < LSEQ; l++) { float d = p[(size_t)l*EIN] - mean; q += d*d; }
    g_means[idx] = mean;
    g_stdev[idx] = sqrtf(q*(1.f/LSEQ) + 1e-5f);
}

// ---------------- build inverted-token matrix (transpose + normalize) --------
__global__ void k_build_tok(const float* __restrict__ x_enc,
                            const float* __restrict__ x_mark) {
    __shared__ float tile[32][33];
    int b = blockIdx.z;
    int n0 = blockIdx.y * 32, l0 = blockIdx.x * 32;
    int tx = threadIdx.x, ty = threadIdx.y;
    int n = n0 + tx, l = l0 + ty;
    float val = 0.f;
    if (n < EIN) {
        float m = g_means[b*EIN + n], sd = g_stdev[b*EIN + n];
        val = (x_enc[(size_t)b*LSEQ*EIN + (size_t)l*EIN + n] - m) / sd;
    } else if (n < NTOK) {
        val = x_mark[(size_t)b*LSEQ*NMARKF + (size_t)l*NMARKF + (n - EIN)];
    }
    tile[ty][tx] = val;
    __syncthreads();
    int nw = n0 + ty, lw = l0 + tx;
    if (nw < TPAD) g_tok[((size_t)b*TPAD + nw)*LSEQ + lw] = tile[tx][ty];
}

// ---------------- fp32 GEMM via packed fma.rn.f32x2 (FFMA2) ------------------
// C = A[M,K] @ W[N,K]^T (+bias)(+relu)(+zeropad). 128x128 tile, 256 threads,
// 8x8 microtile. A stored DUPLICATED in smem ({a,a,b,b} pairs, +4*lm swizzle)
// so the inner loop needs zero splat MOVs: 4x LDS.128 (A pairs) + 2x LDS.128
// (W pairs) + 32 FFMA2 per k. Strictly sequential k-accumulation per output
// element -> bit-identical results to previous rounds (LSH buckets unchanged).
// QKV variant fuses two weight matrices (grid.x = 8; halves 0..3 -> W0/C0,
// 4..7 -> W1/C1) for better wave balance + A-tile L2 reuse.
//
// A-dup layout word index for row k, logical column m (0..127):
//   g(m) = 4*(m & ~1) + 2*(m & 1) + 4*((m>>3)&7)      (row stride 536 words)
// Compute reads ulonglong2 at  4*fm + 4*lm + 8*t  covering m = fm+2t, fm+2t+1.
template<bool RELU, bool ZPAD, bool QKV>
__global__ __launch_bounds__(256, 2)
void k_gemm3(const float* __restrict__ A, const float* __restrict__ W0,
             const float* __restrict__ W1, const float* __restrict__ bias,
             float* __restrict__ C0, float* __restrict__ C1,
             int M, int N, int K) {
    __shared__ __align__(16) float As[2][8][536];
    __shared__ __align__(16) float Ws[2][8][136];
    int tid = threadIdx.x;
    int m0 = blockIdx.y * 128;
    const float* W; float* C; int n0;
    if (QKV) {
        int nb = blockIdx.x;
        W = (nb < 4) ? W0 : W1;
        C = (nb < 4) ? C0 : C1;
        n0 = (nb & 3) * 128;
    } else {
        W = W0; C = C0; n0 = blockIdx.x * 128;
    }

    int r = tid >> 1;                 // row within tile (0..127)
    int kh = (tid & 1) << 2;          // k offset within 8-k stage (0 or 4)
    const float* Ap = A + (size_t)(m0 + r)*K + kh;
    const float* Wq = W + (size_t)(n0 + r)*K + kh;

    int w = tid >> 5, lane = tid & 31;
    int wm = w >> 2, wn = w & 3;
    int lm = lane >> 2, ln = lane & 3;
    int fm = wm*64 + lm*8;
    int fn = wn*32 + ln*8;
    int abase = 4*fm + 4*lm;                                // A read base (words)
    int ga = 4*(r & ~1) + 2*(r & 1) + 4*((r >> 3) & 7);     // A store slot (words)

    ull acc[8][4];
#pragma unroll
    for (int i = 0; i < 8; i++)
#pragma unroll
        for (int j = 0; j < 4; j++) acc[i][j] = 0ull;

    // prologue: stage 0
    float4 a4 = *(const float4*)(Ap);
    float4 w4 = *(const float4*)(Wq);
    {
        float av[4] = {a4.x, a4.y, a4.z, a4.w};
        float wv[4] = {w4.x, w4.y, w4.z, w4.w};
#pragma unroll
        for (int j = 0; j < 4; j++) {
            *(float2*)&As[0][kh+j][ga] = make_float2(av[j], av[j]);
            Ws[0][kh+j][r] = wv[j];
        }
    }
    __syncthreads();

    int nstage = K >> 3;
    int buf = 0;
    for (int s = 0; s < nstage; s++) {
        if (s + 1 < nstage) {
            a4 = *(const float4*)(Ap + (s+1)*8);
            w4 = *(const float4*)(Wq + (s+1)*8);
        }
#pragma unroll
        for (int k = 0; k < 8; k++) {
            ulonglong2 b0 = *(const ulonglong2*)&Ws[buf][k][fn];
            ulonglong2 b1 = *(const ulonglong2*)&Ws[buf][k][fn + 4];
            ull bb[4] = {b0.x, b0.y, b1.x, b1.y};
            ull aa[8];
#pragma unroll
            for (int t = 0; t < 4; t++) {
                ulonglong2 ap = *(const ulonglong2*)&As[buf][k][abase + 8*t];
                aa[2*t] = ap.x; aa[2*t+1] = ap.y;
            }
#pragma unroll
            for (int i = 0; i < 8; i++) {
                asm("fma.rn.f32x2 %0, %1, %2, %0;" : "+l"(acc[i][0]) : "l"(aa[i]), "l"(bb[0]));
                asm("fma.rn.f32x2 %0, %1, %2, %0;" : "+l"(acc[i][1]) : "l"(aa[i]), "l"(bb[1]));
                asm("fma.rn.f32x2 %0, %1, %2, %0;" : "+l"(acc[i][2]) : "l"(aa[i]), "l"(bb[2]));
                asm("fma.rn.f32x2 %0, %1, %2, %0;" : "+l"(acc[i][3]) : "l"(aa[i]), "l"(bb[3]));
            }
        }
        if (s + 1 < nstage) {
            int nb2 = buf ^ 1;
            float av[4] = {a4.x, a4.y, a4.z, a4.w};
            float wv[4] = {w4.x, w4.y, w4.z, w4.w};
#pragma unroll
            for (int j = 0; j < 4; j++) {
                *(float2*)&As[nb2][kh+j][ga] = make_float2(av[j], av[j]);
                Ws[nb2][kh+j][r] = wv[j];
            }
            __syncthreads();
            buf = nb2;
        }
    }

#pragma unroll
    for (int i = 0; i < 8; i++) {
        int m = m0 + fm + i;
        int n = n0 + fn;
        float o[8];
#pragma unroll
        for (int j = 0; j < 4; j++) {
            float lo, hi;
            asm("mov.b64 {%0, %1}, %2;" : "=f"(lo), "=f"(hi) : "l"(acc[i][j]));
            o[2*j] = lo; o[2*j+1] = hi;
        }
        if (bias) {
#pragma unroll
            for (int j = 0; j < 8; j++) o[j] += bias[n + j];
        }
        if (RELU) {
#pragma unroll
            for (int j = 0; j < 8; j++) o[j] = fmaxf(o[j], 0.f);
        }
        if (ZPAD && (m % TPAD) >= NTOK) {
#pragma unroll
            for (int j = 0; j < 8; j++) o[j] = 0.f;
        }
        float4* cp = (float4*)(C + (size_t)m*N + n);
        cp[0] = make_float4(o[0], o[1], o[2], o[3]);
        cp[1] = make_float4(o[4], o[5], o[6], o[7]);
    }
}

// ---------------- LSH hashing: rotated projections + argmax bucket -----------
__global__ void k_hash(const float* __restrict__ rot) {
    int gw = (blockIdx.x * blockDim.x + threadIdx.x) >> 5;
    int lane = threadIdx.x & 31;
    if (gw >= BHD*TPAD) return;
    int bh = gw / TPAD, t = gw % TPAD;
    int b = bh >> 3, hh = bh & 7;
    __shared__ float sq[4][64];
    float* qv = sq[threadIdx.x >> 5];
    const float* qp = g_qk + ((size_t)(b*TPAD + t))*DMODEL + hh*DHEAD;
    qv[lane] = qp[lane];
    qv[lane+32] = qp[lane+32];
    __syncwarp();
    for (int h = 0; h < NHASHR; h++) {
        float bv = -INFINITY; int bi = 0x7fffffff;
        for (int i = lane; i < 65; i += 32) {
            float r = 0.f;
            const float* rp = rot + h*65 + i;
#pragma unroll
            for (int f = 0; f < 64; f++) r = fmaf(qv[f], rp[f*(NHASHR*65)], r);
            if (r > bv || (r == bv && i < bi)) { bv = r; bi = i; }
            float nr = -r;
            if (nr > bv || (nr == bv && (65+i) < bi)) { bv = nr; bi = 65+i; }
        }
        for (int off = 16; off; off >>= 1) {
            float ov = __shfl_xor_sync(0xffffffffu, bv, off);
            int oi = __shfl_xor_sync(0xffffffffu, bi, off);
            if (ov > bv || (ov == bv && oi < bi)) { bv = ov; bi = oi; }
        }
        if (lane == 0) {
            unsigned key = (unsigned)((bi + h*NBKT)*TPAD + t);
            g_keys[(size_t)bh*JTOT + h*TPAD + t] = (key << 12) | (unsigned)(h*TPAD + t);
        }
    }
}

// ---------------- per-row bitonic sort (keys unique => argsort) --------------
__global__ void k_sort() {
    __shared__ unsigned sh[4096];
    int bh = blockIdx.x;
    for (int i = threadIdx.x; i < 4096; i += blockDim.x)
        sh[i] = (i < JTOT) ? g_keys[(size_t)bh*JTOT + i] : 0xffffffffu;
    __syncthreads();
    for (int k = 2; k <= 4096; k <<= 1) {
        for (int j = k >> 1; j > 0; j >>= 1) {
            for (int i = threadIdx.x; i < 4096; i += blockDim.x) {
                int ixj = i ^ j;
                if (ixj > i) {
                    unsigned a = sh[i], c = sh[ixj];
                    bool up = ((i & k) == 0);
                    if ((a > c) == up) { sh[i] = c; sh[ixj] = a; }
                }
            }
            __syncthreads();
        }
    }
    for (int p = threadIdx.x; p < JTOT; p += blockDim.x)
        g_stk[(size_t)bh*JTOT + p] = (int)(sh[p] & 0xfffu);
}

// ---------------- chunked LSH attention (warp per chunk) ---------------------
__global__ void k_attn() {
    __shared__ int   s_key[4][8];
    __shared__ int   s_pos[4][8];
    __shared__ float s_rn[4][8];
    __shared__ float s_k[4][8][64];
    __shared__ float s_v[4][8][64];
    __shared__ float s_p[4][4][8];
    __shared__ float s_l[4][4];
    int gw = (blockIdx.x * blockDim.x + threadIdx.x) >> 5;
    int lane = threadIdx.x & 31;
    int w = threadIdx.x >> 5;
    if (gw >= BHD*NCH) return;
    int bh = gw / NCH, c = gw % NCH;
    int b = bh >> 3, hh = bh & 7;
    if (lane < 8) {
        int src = (lane < 4) ? (c*4 + lane) : (((c + NCH - 1) % NCH)*4 + (lane - 4));
        int sv = g_stk[(size_t)bh*JTOT + src];
        s_key[w][lane] = sv;
        s_pos[w][lane] = sv % TPAD;
    }
    __syncwarp();
#pragma unroll
    for (int j = 0; j < 8; j++) {
        size_t base = ((size_t)(b*TPAD + s_pos[w][j]))*DMODEL + hh*DHEAD;
        s_k[w][j][lane]    = g_qk[base + lane];
        s_k[w][j][lane+32] = g_qk[base + lane + 32];
        s_v[w][j][lane]    = g_vv[base + lane];
        s_v[w][j][lane+32] = g_vv[base + lane + 32];
    }
    __syncwarp();
    if (lane < 8) {
        float s = 0.f;
#pragma unroll
        for (int f = 0; f < 64; f++) s += s_k[w][lane][f]*s_k[w][lane][f];
        s_rn[w][lane] = rsqrtf(fmaxf(s, 1e-24f));
    }
    __syncwarp();
    int qi = lane >> 3, kj = lane & 7;
    float d = 0.f;
#pragma unroll
    for (int f = 0; f < 64; f++) d = fmaf(s_k[w][qi][f], s_k[w][kj][f], d);
    d *= s_rn[w][kj] * 0.125f;
    if (s_pos[w][qi] == s_pos[w][kj]) d = -50000.f;
    float m = d;
    m = fmaxf(m, __shfl_xor_sync(0xffffffffu, m, 4));
    m = fmaxf(m, __shfl_xor_sync(0xffffffffu, m, 2));
    m = fmaxf(m, __shfl_xor_sync(0xffffffffu, m, 1));
    float e = expf(d - m);
    float s = e;
    s += __shfl_xor_sync(0xffffffffu, s, 4);
    s += __shfl_xor_sync(0xffffffffu, s, 2);
    s += __shfl_xor_sync(0xffffffffu, s, 1);
    s_p[w][qi][kj] = e / s;
    if (kj == 0) s_l[w][qi] = m + logf(s);
    __syncwarp();
#pragma unroll
    for (int i = 0; i < 4; i++) {
        float a0 = 0.f, a1 = 0.f;
#pragma unroll
        for (int j = 0; j < 8; j++) {
            float p = s_p[w][i][j];
            a0 = fmaf(p, s_v[w][j][lane],    a0);
            a1 = fmaf(p, s_v[w][j][lane+32], a1);
        }
        int jl = s_key[w][i];
        int hr = jl / TPAD, tp = jl % TPAD;
        float* op = g_oh + (((size_t)bh*NHASHR + hr)*TPAD + tp)*DHEAD;
        op[lane] = a0;
        op[lane+32] = a1;
        if (lane == 0) g_lse[((size_t)bh*NHASHR + hr)*TPAD + tp] = s_l[w][i];
    }
}

// ---------------- combine hash rounds (softmax over lse), 4 tokens/block -----
__global__ void k_combine(float* __restrict__ attn) {
    int id = blockIdx.x * 4 + (threadIdx.x >> 6);
    int f = threadIdx.x & 63;
    int bh = id / TPAD, t = id % TPAD;
    int b = bh >> 3, hh = bh & 7;
    float l0 = g_lse[((size_t)bh*NHASHR + 0)*TPAD + t];
    float l1 = g_lse[((size_t)bh*NHASHR + 1)*TPAD + t];
    float l2 = g_lse[((size_t)bh*NHASHR + 2)*TPAD + t];
    float l3 = g_lse[((size_t)bh*NHASHR + 3)*TPAD + t];
    float m = fmaxf(fmaxf(l0, l1), fmaxf(l2, l3));
    float e0 = expf(l0-m), e1 = expf(l1-m), e2 = expf(l2-m), e3 = expf(l3-m);
    float inv = 1.f / (e0+e1+e2+e3);
    float acc =
        e0*inv*g_oh[(((size_t)bh*NHASHR + 0)*TPAD + t)*DHEAD + f] +
        e1*inv*g_oh[(((size_t)bh*NHASHR + 1)*TPAD + t)*DHEAD + f] +
        e2*inv*g_oh[(((size_t)bh*NHASHR + 2)*TPAD + t)*DHEAD + f] +
        e3*inv*g_oh[(((size_t)bh*NHASHR + 3)*TPAD + t)*DHEAD + f];
    attn[((size_t)(b*TPAD + t))*DMODEL + hh*DHEAD + f] = acc;
}

// ---------------- block reduce helper ----------------------------------------
__device__ __forceinline__ float blk_red(float v, float* sred) {
    for (int o = 16; o; o >>= 1) v += __shfl_xor_sync(0xffffffffu, v, o);
    if ((threadIdx.x & 31) == 0) sred[threadIdx.x >> 5] = v;
    __syncthreads();
    float r = sred[0] + sred[1] + sred[2] + sred[3];
    __syncthreads();
    return r;
}

// ---------------- residual add + LayerNorm (rows n < 516) --------------------
__global__ void k_addln(float* __restrict__ x, const float* __restrict__ y,
                        const float* __restrict__ gam, const float* __restrict__ bet) {
    __shared__ float sred[4];
    int r = blockIdx.x;
    int b = r / NTOK, n = r % NTOK;
    float* xr = x + ((size_t)(b*TPAD + n))*DMODEL;
    const float* yr = y + ((size_t)(b*TPAD + n))*DMODEL;
    int tid = threadIdx.x;
    float v[4]; float s = 0.f;
#pragma unroll
    for (int i = 0; i < 4; i++) { int f = tid + i*128; v[i] = xr[f] + yr[f]; s += v[i]; }
    float mean = blk_red(s, sred) * (1.f/DMODEL);
    float q = 0.f;
#pragma unroll
    for (int i = 0; i < 4; i++) { float dd = v[i]-mean; q += dd*dd; }
    float var = blk_red(q, sred) * (1.f/DMODEL);
    float rs = rsqrtf(var + 1e-5f);
#pragma unroll
    for (int i = 0; i < 4; i++) {
        int f = tid + i*128;
        xr[f] = (v[i]-mean)*rs*gam[f] + bet[f];
    }
}

// ---------------- final LN on last token + projection ------------------------
__global__ void k_final(const float* __restrict__ gF, const float* __restrict__ bF,
                        const float* __restrict__ Wp, const float* __restrict__ bp) {
    __shared__ float sred[4];
    int b = blockIdx.x, tid = threadIdx.x;
    const float* xr = g_x + ((size_t)(b*TPAD + NTOK - 1))*DMODEL;
    float v[4]; float s = 0.f;
#pragma unroll
    for (int i = 0; i < 4; i++) { int f = tid + i*128; v[i] = xr[f]; s += v[i]; }
    float mean = blk_red(s, sred) * (1.f/DMODEL);
    float q = 0.f;
#pragma unroll
    for (int i = 0; i < 4; i++) { float dd = v[i]-mean; q += dd*dd; }
    float var = blk_red(q, sred) * (1.f/DMODEL);
    float rs = rsqrtf(var + 1e-5f);
    float dot = 0.f;
#pragma unroll
    for (int i = 0; i < 4; i++) {
        int f = tid + i*128;
        float nx = (v[i]-mean)*rs*gF[f] + bF[f];
        dot = fmaf(nx, Wp[f], dot);
    }
    float tot = blk_red(dot, sred);
    if (tid == 0) g_dec[b] = tot + bp[0];
}

// ---------------- output: dec[j]*stdev[i,e] + means[i,e] ---------------------
__global__ void k_out(float* __restrict__ out) {
    int idx = blockIdx.x * blockDim.x + threadIdx.x;
    if (idx >= BB*BB*EIN) return;
    int e = idx & 511;
    int j = (idx >> 9) & 31;
    int i = idx >> 14;
    out[idx] = g_dec[j]*g_stdev[i*EIN + e] + g_means[i*EIN + e];
}

// ---------------- host-side orchestration ------------------------------------
extern "C" void kernel_launch(void* const* d_in, const int* in_sizes, int n_in,
                              void* d_out, int out_size) {
    const float* x_enc  = (const float*)d_in[0];
    const float* x_mark = (const float*)d_in[1];
    const float* W_emb  = (const float*)d_in[2];
    const float* b_emb  = (const float*)d_in[3];
    const float* Wqk    = (const float*)d_in[4];
    const float* Wv     = (const float*)d_in[5];
    const float* Wo     = (const float*)d_in[6];
    const float* bo     = (const float*)d_in[7];
    const float* Wc1    = (const float*)d_in[8];
    const float* bc1    = (const float*)d_in[9];
    const float* Wc2    = (const float*)d_in[10];
    const float* bc2    = (const float*)d_in[11];
    const float* g1     = (const float*)d_in[12];
    const float* b1     = (const float*)d_in[13];
    const float* g2     = (const float*)d_in[14];
    const float* b2     = (const float*)d_in[15];
    const float* gF     = (const float*)d_in[16];
    const float* bF     = (const float*)d_in[17];
    const float* Wp     = (const float*)d_in[18];
    const float* bp     = (const float*)d_in[19];
    const float* rot    = (const float*)d_in[20];

    float *p_tok, *p_x, *p_qk, *p_v, *p_t2, *p_ff;
    cudaGetSymbolAddress((void**)&p_tok, g_tok);
    cudaGetSymbolAddress((void**)&p_x,   g_x);
    cudaGetSymbolAddress((void**)&p_qk,  g_qk);
    cudaGetSymbolAddress((void**)&p_v,   g_vv);
    cudaGetSymbolAddress((void**)&p_t2,  g_t2);
    cudaGetSymbolAddress((void**)&p_ff,  g_ff);

    // 1. RevIN stats
    k_revin<<<(BB*EIN + 255)/256, 256>>>(x_enc);
    // 2. token matrix (normalize + transpose + marks)
    k_build_tok<<<dim3(16, 17, BB), dim3(32, 32)>>>(x_enc, x_mark);
    // 3. embedding (+ zero pad rows in epilogue)
    k_gemm3<false, true, false><<<dim3(4, 130), 256>>>(
        p_tok, W_emb, nullptr, b_emb, p_x, nullptr, MROWS, DMODEL, LSEQ);

    for (int l = 0; l < 2; l++) {
        const float* Wqk_l = Wqk + (size_t)l*DMODEL*DMODEL;
        const float* Wv_l  = Wv  + (size_t)l*DMODEL*DMODEL;
        const float* Wo_l  = Wo  + (size_t)l*DMODEL*DMODEL;
        const float* bo_l  = bo  + (size_t)l*DMODEL;
        const float* Wc1_l = Wc1 + (size_t)l*DFFN*DMODEL;
        const float* bc1_l = bc1 + (size_t)l*DFFN;
        const float* Wc2_l = Wc2 + (size_t)l*DMODEL*DFFN;
        const float* bc2_l = bc2 + (size_t)l*DMODEL;
        const float* rot_l = rot + (size_t)l*DHEAD*NHASHR*65;

        // fused QK + V projection
        k_gemm3<false, false, true><<<dim3(8, 130), 256>>>(
            p_x, Wqk_l, Wv_l, nullptr, p_qk, p_v, MROWS, DMODEL, DMODEL);
        k_hash<<<(BHD*TPAD*32)/128, 128>>>(rot_l);
        k_sort<<<BHD, 512>>>();
        k_attn<<<(BHD*NCH*32)/128, 128>>>();
        k_combine<<<(BHD*TPAD)/4, 256>>>(p_ff);
        k_gemm3<false, false, false><<<dim3(4, 130), 256>>>(
            p_ff, Wo_l, nullptr, bo_l, p_t2, nullptr, MROWS, DMODEL, DMODEL);
        k_addln<<<BB*NTOK, 128>>>(p_x, p_t2, g1 + l*DMODEL, b1 + l*DMODEL);
        k_gemm3<true, false, false><<<dim3(16, 130), 256>>>(
            p_x, Wc1_l, nullptr, bc1_l, p_ff, nullptr, MROWS, DFFN, DMODEL);
        k_gemm3<false, false, false><<<dim3(4, 130), 256>>>(
            p_ff, Wc2_l, nullptr, bc2_l, p_t2, nullptr, MROWS, DMODEL, DFFN);
        k_addln<<<BB*NTOK, 128>>>(p_x, p_t2, g2 + l*DMODEL, b2 + l*DMODEL);
    }

    k_final<<<BB, 128>>>(gF, bF, Wp, bp);
    k_out<<<(BB*BB*EIN + 255)/256, 256>>>((float*)d_out);
}